// round 9
// baseline (speedup 1.0000x reference)
#include <cuda_runtime.h>
#include <cstdint>

#define DIM   512
#define BATCH 32
#define TT    2048
#define G4    2048              // 4*DIM
#define NBLK  128               // persistent blocks for recurrence
#define RTHR  512
#define GRPS  4                 // independent batch groups
#define GRPB  32                // blocks per group
#define GBAT  8                 // batches per group
#define HGRP  4096              // floats of h per group (512 dims x 8 b)

// ---------------- device scratch (no allocations allowed) ----------------
__device__ __align__(16) float g_xg[(size_t)TT * G4 * BATCH];   // [t][n][b]
__device__ __align__(16) float g_hbuf[4][GRPS * HGRP];          // 4-deep ring
__device__ unsigned g_flag[NBLK * 8];   // one flag per block, 32B apart

typedef unsigned long long ull;

// ---------------- f32x2 helpers ----------------
__device__ __forceinline__ ull f2fma(ull a, ull b, ull c){
    ull d; asm("fma.rn.f32x2 %0, %1, %2, %3;" : "=l"(d) : "l"(a), "l"(b), "l"(c)); return d;
}
__device__ __forceinline__ ull pk2(float lo, float hi){
    ull r; asm("mov.b64 %0, {%1, %2};" : "=l"(r) : "f"(lo), "f"(hi)); return r;
}
__device__ __forceinline__ float2 upk(ull v){
    float2 f; asm("mov.b64 {%0, %1}, %2;" : "=f"(f.x), "=f"(f.y) : "l"(v)); return f;
}
__device__ __forceinline__ float hadd(ull v){ float2 f = upk(v); return f.x + f.y; }

__device__ __forceinline__ float sigf(float x){ return 1.0f / (1.0f + __expf(-x)); }
__device__ __forceinline__ float tanhfast(float x){
    float e = __expf(2.0f * x);              // inf-safe at both ends
    return 1.0f - 2.0f / (e + 1.0f);
}

// ---------------- scoped sync primitives ----------------
__device__ __forceinline__ void st_release(unsigned* p, unsigned v){
    asm volatile("st.release.gpu.global.u32 [%0], %1;" :: "l"(p), "r"(v) : "memory");
}
__device__ __forceinline__ unsigned ld_acquire(unsigned* p){
    unsigned v;
    asm volatile("ld.acquire.gpu.global.u32 %0, [%1];" : "=r"(v) : "l"(p) : "memory");
    return v;
}
__device__ __forceinline__ void cpa16(unsigned dst, const void* src){
    asm volatile("cp.async.cg.shared.global [%0], [%1], 16;" :: "r"(dst), "l"(src));
}

// =====================================================================
// Kernel 1: xg[t][n][b] = sum_k x[b][t][k]*W_ih[n][k] + b_ih[n] + b_hh[n]
// M = 65536 (m = t*32 + b), N = 2048, K = 512. 128x128x8 tile, f32x2.
// Block (0,0) also re-initializes recurrence state each launch.
// =====================================================================
__global__ void __launch_bounds__(256) gemm_xg_kernel(
    const float* __restrict__ x, const float* __restrict__ Wih,
    const float* __restrict__ bih, const float* __restrict__ bhh)
{
    __shared__ float As[8][128];
    __shared__ float Bs[8][128];
    const int tid = threadIdx.x;

    if (blockIdx.x == 0 && blockIdx.y == 0){     // init (runs before rec kernel)
        for (int i = tid; i < GRPS * HGRP; i += 256) g_hbuf[0][i] = 0.0f;
        for (int i = tid; i < NBLK; i += 256) g_flag[i * 8] = 0u;
    }

    const int bn0 = blockIdx.x * 128;
    const int bm0 = blockIdx.y * 128;
    const int tm0 = (tid >> 4) * 8;
    const int c4  = (tid & 15) * 4;

    const int lr = tid >> 1;
    const int lk = (tid & 1) * 4;
    const int m  = bm0 + lr;
    const float* ap = x + (size_t)(m & 31) * ((size_t)TT * DIM) + (size_t)(m >> 5) * DIM + lk;
    const float* bp = Wih + (size_t)(bn0 + lr) * DIM + lk;

    ull c2[4][8];
    #pragma unroll
    for (int i = 0; i < 4; i++)
        #pragma unroll
        for (int j = 0; j < 8; j++) c2[i][j] = 0ULL;

    float4 av = *(const float4*)ap;
    float4 bv = *(const float4*)bp;

    for (int k0 = 0; k0 < DIM; k0 += 8){
        As[lk+0][lr]=av.x; As[lk+1][lr]=av.y; As[lk+2][lr]=av.z; As[lk+3][lr]=av.w;
        Bs[lk+0][lr]=bv.x; Bs[lk+1][lr]=bv.y; Bs[lk+2][lr]=bv.z; Bs[lk+3][lr]=bv.w;
        __syncthreads();
        if (k0 + 8 < DIM){
            av = *(const float4*)(ap + k0 + 8);
            bv = *(const float4*)(bp + k0 + 8);
        }
        #pragma unroll
        for (int kk = 0; kk < 8; kk++){
            const ulonglong2* arow = (const ulonglong2*)&As[kk][tm0];
            ulonglong2 a01 = arow[0];
            ulonglong2 a23 = arow[1];
            float4 bl = *(const float4*)&Bs[kk][c4];
            float4 bh = *(const float4*)&Bs[kk][c4 + 64];
            ull bd[8];
            bd[0]=pk2(bl.x,bl.x); bd[1]=pk2(bl.y,bl.y); bd[2]=pk2(bl.z,bl.z); bd[3]=pk2(bl.w,bl.w);
            bd[4]=pk2(bh.x,bh.x); bd[5]=pk2(bh.y,bh.y); bd[6]=pk2(bh.z,bh.z); bd[7]=pk2(bh.w,bh.w);
            #pragma unroll
            for (int j = 0; j < 8; j++){
                c2[0][j] = f2fma(a01.x, bd[j], c2[0][j]);
                c2[1][j] = f2fma(a01.y, bd[j], c2[1][j]);
                c2[2][j] = f2fma(a23.x, bd[j], c2[2][j]);
                c2[3][j] = f2fma(a23.y, bd[j], c2[3][j]);
            }
        }
        __syncthreads();
    }

    float bias[8];
    #pragma unroll
    for (int j = 0; j < 8; j++){
        int n = bn0 + c4 + (j & 3) + ((j >> 2) << 6);
        bias[j] = bih[n] + bhh[n];
    }
    #pragma unroll
    for (int i = 0; i < 8; i++){
        int mg = bm0 + tm0 + i;
        size_t obase = (size_t)(mg >> 5) * ((size_t)G4 * BATCH) + (size_t)(mg & 31);
        #pragma unroll
        for (int j = 0; j < 8; j++){
            float2 p = upk(c2[i >> 1][j]);
            float v = (i & 1) ? p.y : p.x;
            int n = bn0 + c4 + (j & 3) + ((j >> 2) << 6);
            g_xg[obase + (size_t)n * BATCH] = v + bias[j];
        }
    }
}

// =====================================================================
// Kernel 2: persistent recurrence, batch-split into 4 independent
// groups of 32 blocks (group grp = bx>>5 owns batches [grp*8,+8);
// block gb = bx&31 owns dims [gb*16,+16), all 4 gates; W_hh slice =
// 64 rows = 132KB in shared). 512 threads = 16 warps; warp kh owns
// k-slice [kh*32,+32); lane = (bh = l&1 -> batches bh+2j, dl = l>>1
// -> dim). Thread: 4 gates x 4 batches x 1 dim over 32 k.
// Warp kh's h slice is produced by group blocks 2kh, 2kh+1 -> poll
// 2 flags, cp.async own 1KB slice, FMA. Reduce slot = g*144+d*9+b
// (stride-9, conflict-light). Owners (tid<128: b=tid>>4, d=tid&15)
// update c, store h, 128-thread named bar, release, out store.
// =====================================================================
__global__ void __launch_bounds__(RTHR) lstm_rec_kernel(
    const float* __restrict__ Whh, float* __restrict__ out)
{
    extern __shared__ float sm[];
    float* shW = sm;                       // 64 rows x 516 floats (padded)
    float* shH = shW + 64 * 516;           // [128 k4][8 b][4] = 4096 floats
    float* shR = shH + HGRP;               // [16 kh][580] partials
    float* shG = shR + 16 * 580;           // [4 g][slot 144]

    const int tid  = threadIdx.x;
    const int bx   = blockIdx.x;
    const int grp  = bx >> 5;
    const int gb   = bx & 31;
    const int kh   = tid >> 5;             // warp id = k-slice
    const int lane = tid & 31;
    const int bh   = lane & 1;
    const int dl   = lane >> 1;

    // Load this block's 64 W_hh rows into padded shared (once).
    for (int idx = tid; idx < 64 * 128; idx += RTHR){
        int rl = idx >> 7;                 // g*16 + dloc
        int k4 = idx & 127;
        int g = rl >> 4, dloc = rl & 15;
        *(float4*)(shW + rl * 516 + k4 * 4) =
            *(const float4*)(Whh + (size_t)(g * DIM + gb * 16 + dloc) * DIM + k4 * 4);
    }

    const ulonglong2* w0 = (const ulonglong2*)(shW + (0*16 + dl) * 516 + kh * 32);
    const ulonglong2* w1 = (const ulonglong2*)(shW + (1*16 + dl) * 516 + kh * 32);
    const ulonglong2* w2 = (const ulonglong2*)(shW + (2*16 + dl) * 516 + kh * 32);
    const ulonglong2* w3 = (const ulonglong2*)(shW + (3*16 + dl) * 516 + kh * 32);
    // h as ulonglong2: idx = k4*8 + b ; this thread starts at batch bh
    const ulonglong2* hp = ((const ulonglong2*)shH) + kh * 64 + bh;

    // staging: warp kh stages its 1KB slice (64 float4), 2 per lane
    const unsigned stg =
        (unsigned)__cvta_generic_to_shared(shH) + (unsigned)(kh * 64 + lane) * 16u;
    const int stg_src = grp * (HGRP / 4) + kh * 64 + lane;    // float4 index

    // poll: producers of k-slice kh are group blocks 2kh, 2kh+1
    unsigned* pf = &g_flag[(grp * GRPB + kh * 2 + (lane & 1)) * 8];

    // reduce role: thread -> (rg, rd, rb), slot = rg*144 + rd*9 + rb
    const int rg = tid >> 7;
    const int rd = (tid >> 3) & 15;
    const int rb = tid & 7;
    const int r_slot = rg * 144 + rd * 9 + rb;
    const size_t xoffs = (size_t)(rg * DIM + gb * 16 + rd) * BATCH
                       + (size_t)(grp * GBAT + rb);

    // owner role (tid < 128): ob = tid>>4 (local batch), od = tid&15
    const int ob = tid >> 4, od = tid & 15;
    const int D  = gb * 16 + od;
    const int Bg = grp * GBAT + ob;
    const int hwidx = grp * HGRP + (D >> 2) * (GBAT * 4) + ob * 4 + (D & 3);
    float* outp = out + (size_t)Bg * ((size_t)TT * DIM) + D;
    unsigned* myflag = &g_flag[(grp * GRPB + gb) * 8];

    float cc = 0.0f;
    __syncthreads();                       // W ready

    for (int t = 0; t < TT; t++){
        // xg prefetch (independent of h)
        float xv = __ldcg(g_xg + (size_t)t * ((size_t)G4 * BATCH) + xoffs);

        // ---- per-warp poll: my 2 producers reached step t ----
        if (lane < 2){
            while (ld_acquire(pf) < (unsigned)t) { }
        }
        __syncwarp();

        // ---- stage my 1KB h slice via cp.async ----
        const float4* hsrc = (const float4*)g_hbuf[t & 3] + stg_src;
        cpa16(stg,        hsrc);
        cpa16(stg + 512u, hsrc + 32);
        asm volatile("cp.async.commit_group;");
        asm volatile("cp.async.wait_group 0;");
        __syncwarp();

        // ---- partial gates: 4 gates x 4 batches x 1 dim over 32 k ----
        ull acc[4][4];
        #pragma unroll
        for (int g = 0; g < 4; g++)
            #pragma unroll
            for (int j = 0; j < 4; j++) acc[g][j] = 0ULL;

        #pragma unroll
        for (int i = 0; i < 8; i++){
            ulonglong2 h0 = hp[i * 8];
            ulonglong2 h1 = hp[i * 8 + 2];
            ulonglong2 h2 = hp[i * 8 + 4];
            ulonglong2 h3 = hp[i * 8 + 6];
            ulonglong2 v0 = w0[i], v1 = w1[i], v2 = w2[i], v3 = w3[i];
            acc[0][0]=f2fma(h0.x,v0.x,acc[0][0]); acc[0][0]=f2fma(h0.y,v0.y,acc[0][0]);
            acc[0][1]=f2fma(h1.x,v0.x,acc[0][1]); acc[0][1]=f2fma(h1.y,v0.y,acc[0][1]);
            acc[0][2]=f2fma(h2.x,v0.x,acc[0][2]); acc[0][2]=f2fma(h2.y,v0.y,acc[0][2]);
            acc[0][3]=f2fma(h3.x,v0.x,acc[0][3]); acc[0][3]=f2fma(h3.y,v0.y,acc[0][3]);
            acc[1][0]=f2fma(h0.x,v1.x,acc[1][0]); acc[1][0]=f2fma(h0.y,v1.y,acc[1][0]);
            acc[1][1]=f2fma(h1.x,v1.x,acc[1][1]); acc[1][1]=f2fma(h1.y,v1.y,acc[1][1]);
            acc[1][2]=f2fma(h2.x,v1.x,acc[1][2]); acc[1][2]=f2fma(h2.y,v1.y,acc[1][2]);
            acc[1][3]=f2fma(h3.x,v1.x,acc[1][3]); acc[1][3]=f2fma(h3.y,v1.y,acc[1][3]);
            acc[2][0]=f2fma(h0.x,v2.x,acc[2][0]); acc[2][0]=f2fma(h0.y,v2.y,acc[2][0]);
            acc[2][1]=f2fma(h1.x,v2.x,acc[2][1]); acc[2][1]=f2fma(h1.y,v2.y,acc[2][1]);
            acc[2][2]=f2fma(h2.x,v2.x,acc[2][2]); acc[2][2]=f2fma(h2.y,v2.y,acc[2][2]);
            acc[2][3]=f2fma(h3.x,v2.x,acc[2][3]); acc[2][3]=f2fma(h3.y,v2.y,acc[2][3]);
            acc[3][0]=f2fma(h0.x,v3.x,acc[3][0]); acc[3][0]=f2fma(h0.y,v3.y,acc[3][0]);
            acc[3][1]=f2fma(h1.x,v3.x,acc[3][1]); acc[3][1]=f2fma(h1.y,v3.y,acc[3][1]);
            acc[3][2]=f2fma(h2.x,v3.x,acc[3][2]); acc[3][2]=f2fma(h2.y,v3.y,acc[3][2]);
            acc[3][3]=f2fma(h3.x,v3.x,acc[3][3]); acc[3][3]=f2fma(h3.y,v3.y,acc[3][3]);
        }

        // ---- partials: shR[kh][g*144 + dl*9 + (bh+2j)] ----
        #pragma unroll
        for (int g = 0; g < 4; g++)
            #pragma unroll
            for (int j = 0; j < 4; j++)
                shR[kh * 580 + g * 144 + dl * 9 + bh + 2*j] = hadd(acc[g][j]);
        __syncthreads();                   // bar1: all partials in

        // ---- reduce over 16 kh + nonlinearity (all 512 threads) ----
        {
            float s = xv;
            #pragma unroll
            for (int k = 0; k < 16; k++) s += shR[k * 580 + r_slot];
            shG[r_slot] = (rg == 2) ? tanhfast(s) : sigf(s);
        }
        __syncthreads();                   // bar2: gates ready

        // ---- owners: c/h update, store h, release; others loop on ----
        if (tid < 128){
            float iv = shG[  0 + od * 9 + ob];
            float fv = shG[144 + od * 9 + ob];
            float gv = shG[288 + od * 9 + ob];
            float ov = shG[432 + od * 9 + ob];
            cc = fv * cc + iv * gv;
            float hv = ov * tanhfast(cc);
            g_hbuf[(t + 1) & 3][hwidx] = hv;
            asm volatile("bar.sync 1, 128;");          // owners only
            if (tid == 0 && t + 1 < TT)
                st_release(myflag, (unsigned)(t + 1));
            outp[(size_t)t * DIM] = hv;                // overlaps next poll
        }
    }
}

// =====================================================================
extern "C" void kernel_launch(void* const* d_in, const int* in_sizes, int n_in,
                              void* d_out, int out_size)
{
    (void)in_sizes; (void)n_in; (void)out_size;
    const float* x    = (const float*)d_in[0];
    const float* Wih  = (const float*)d_in[1];
    const float* Whh  = (const float*)d_in[2];
    const float* bih  = (const float*)d_in[3];
    const float* bhh  = (const float*)d_in[4];
    float* out = (float*)d_out;

    // shW 64*516 + shH 4096 + shR 16*580 + shG 576 = 46976 floats = 187904 B
    cudaFuncSetAttribute(lstm_rec_kernel,
                         cudaFuncAttributeMaxDynamicSharedMemorySize, 187904);

    dim3 ggrid(G4 / 128, (BATCH * TT) / 128);
    gemm_xg_kernel<<<ggrid, 256>>>(x, Wih, bih, bhh);
    lstm_rec_kernel<<<NBLK, RTHR, 187904>>>(Whh, out);
}